// round 1
// baseline (speedup 1.0000x reference)
#include <cuda_runtime.h>
#include <math_constants.h>

// Problem constants (fixed by reference)
#define NN      100000      // nodes
#define EE      3200000     // edges
#define CYD     128         // signal channels
#define H1      512         // mlp_in hidden
#define FD      10          // node feature dim after mlp_in
#define HC      20          // heads * out_channels (2*10)
#define H2      512         // mlp_out hidden
#define TILE_R  16          // rows per block in GEMM kernels

// ---------------- device scratch (no allocations allowed) ----------------
__device__ float    g_x2[NN * FD];        // mlp_in output            (4 MB)
__device__ float    g_xl[NN * HC];        // GAT source transform     (8 MB)
__device__ float    g_xr[NN * HC];        // GAT target transform     (8 MB)
__device__ float    g_alpha[EE * 2];      // per-edge attention logit (25.6 MB)
__device__ unsigned g_m[NN * 2];          // per-(dst,head) max, ordered-uint
__device__ float    g_den[NN * 2];        // softmax denominator
__device__ float    g_num[NN * HC];       // unnormalized numerator   (8 MB)
__device__ int      g_mask_mode;          // 0=uint8, 1=int32, 2=float32

// ordered-uint encoding so unsigned atomicMax == float max
__device__ __forceinline__ unsigned fenc(float f) {
    unsigned u = __float_as_uint(f);
    return (u & 0x80000000u) ? ~u : (u | 0x80000000u);
}
__device__ __forceinline__ float fdec(unsigned u) {
    return (u & 0x80000000u) ? __uint_as_float(u ^ 0x80000000u)
                             : __uint_as_float(~u);
}

// ---------------- mask dtype detection (jax bool marshalling unknown) ----
__global__ void k_detect(const unsigned* __restrict__ mw) {
    __shared__ int notInt, notFloat;
    if (threadIdx.x == 0) { notInt = 0; notFloat = 0; }
    __syncthreads();
    unsigned v = mw[threadIdx.x];   // 256 words = first 1 KB of the buffer
    if (v > 1u)                         atomicOr(&notInt, 1);
    if (v != 0u && v != 0x3f800000u)    atomicOr(&notFloat, 1);
    __syncthreads();
    if (threadIdx.x == 0)
        g_mask_mode = notInt ? (notFloat ? 0 : 2) : 1;
}

// ---------------- init accumulators each call (deterministic) ------------
__global__ void k_init() {
    int i = blockIdx.x * blockDim.x + threadIdx.x;
    if (i < NN * HC) g_num[i] = 0.f;
    if (i < NN * 2) { g_den[i] = 0.f; g_m[i] = fenc(-CUDART_INF_F); }
}

// ---------------- kernel A: mask -> Linear(128,512) -> BN -> ReLU -> Linear(512,10)
__global__ void __launch_bounds__(128)
k_mlp_in(const float* __restrict__ signal, const void* __restrict__ mask,
         const float* __restrict__ W1, const float* __restrict__ b1,
         const float* __restrict__ gamma, const float* __restrict__ beta,
         const float* __restrict__ W2, const float* __restrict__ b2)
{
    __shared__ float xs[TILE_R][CYD];
    __shared__ float hs[TILE_R][H1 + 1];
    const int t = threadIdx.x;
    const int row0 = blockIdx.x * TILE_R;
    const int mode = g_mask_mode;

    #pragma unroll
    for (int r = 0; r < TILE_R; r++) {
        int n = row0 + r;
        bool mk;
        if (mode == 0)       mk = ((const unsigned char*)mask)[n] != 0;
        else if (mode == 1)  mk = ((const int*)mask)[n] != 0;
        else                 mk = ((const float*)mask)[n] != 0.f;
        xs[r][t] = mk ? 0.f : signal[n * CYD + t];
    }
    __syncthreads();

    float acc[4][TILE_R];
    #pragma unroll
    for (int j = 0; j < 4; j++)
        #pragma unroll
        for (int r = 0; r < TILE_R; r++) acc[j][r] = 0.f;

    #pragma unroll 4
    for (int k = 0; k < CYD; k++) {
        float w0 = W1[k * H1 + t];
        float w1 = W1[k * H1 + t + 128];
        float w2 = W1[k * H1 + t + 256];
        float w3 = W1[k * H1 + t + 384];
        #pragma unroll
        for (int r = 0; r < TILE_R; r++) {
            float xv = xs[r][k];
            acc[0][r] += xv * w0;
            acc[1][r] += xv * w1;
            acc[2][r] += xv * w2;
            acc[3][r] += xv * w3;
        }
    }
    const float inv = rsqrtf(1.f + 1e-5f);
    #pragma unroll
    for (int j = 0; j < 4; j++) {
        int h = t + 128 * j;
        float s  = gamma[h] * inv;
        float bb = beta[h];
        float bi = b1[h];
        #pragma unroll
        for (int r = 0; r < TILE_R; r++) {
            float v = (acc[j][r] + bi) * s + bb;
            hs[r][h] = v > 0.f ? v : 0.f;
        }
    }
    __syncthreads();

    // x2 = hs @ W2 + b2   (16x10 outputs)
    for (int o = t; o < TILE_R * FD; o += 128) {
        int r = o / FD, c = o % FD;
        float a = b2[c];
        #pragma unroll 8
        for (int h = 0; h < H1; h++) a += hs[r][h] * W2[h * FD + c];
        g_x2[(row0 + r) * FD + c] = a;
    }
}

// ---------------- kernel B: xl = x2@Wl+bl ; xr = x2@Wr+br ----------------
__global__ void k_gat_lin(const float* __restrict__ Wl, const float* __restrict__ bl,
                          const float* __restrict__ Wr, const float* __restrict__ br)
{
    int i = blockIdx.x * blockDim.x + threadIdx.x;     // over N*HC
    if (i >= NN * HC) return;
    int n = i / HC, j = i % HC;
    const float* x = &g_x2[n * FD];
    float al = bl[j], ar = br[j];
    #pragma unroll
    for (int k = 0; k < FD; k++) {
        float xv = x[k];
        al += xv * Wl[k * HC + j];
        ar += xv * Wr[k * HC + j];
    }
    g_xl[i] = al;
    g_xr[i] = ar;
}

// ---------------- kernel C1: per-edge attention logit + segment max ------
__global__ void k_edge1(const int* __restrict__ ei, const float* __restrict__ ew,
                        const float* __restrict__ We, const float* __restrict__ att)
{
    int e = blockIdx.x * blockDim.x + threadIdx.x;
    if (e >= EE) return;
    int src = ei[e], dst = ei[EE + e];
    float w = ew[e];
    const float4* xl4 = (const float4*)&g_xl[src * HC];
    const float4* xr4 = (const float4*)&g_xr[dst * HC];
    float a0 = 0.f, a1 = 0.f;
    #pragma unroll
    for (int q = 0; q < 5; q++) {
        float4 l = xl4[q], r = xr4[q];
        float vv[4] = { l.x + r.x, l.y + r.y, l.z + r.z, l.w + r.w };
        #pragma unroll
        for (int u = 0; u < 4; u++) {
            int j = q * 4 + u;
            float v = vv[u] + w * We[j];
            v = v > 0.f ? v : 0.2f * v;               // leaky_relu(., 0.2)
            if (j < 10) a0 += v * att[j];
            else        a1 += v * att[j];
        }
    }
    g_alpha[2 * e]     = a0;
    g_alpha[2 * e + 1] = a1;
    atomicMax(&g_m[dst * 2],     fenc(a0));
    atomicMax(&g_m[dst * 2 + 1], fenc(a1));
}

// ---------------- kernel C2: exp + unnormalized scatter-accumulate -------
__global__ void k_edge2(const int* __restrict__ ei)
{
    int e = blockIdx.x * blockDim.x + threadIdx.x;
    if (e >= EE) return;
    int src = ei[e], dst = ei[EE + e];
    float ex0 = expf(g_alpha[2 * e]     - fdec(g_m[dst * 2]));
    float ex1 = expf(g_alpha[2 * e + 1] - fdec(g_m[dst * 2 + 1]));
    atomicAdd(&g_den[dst * 2],     ex0);
    atomicAdd(&g_den[dst * 2 + 1], ex1);
    const float4* xl4 = (const float4*)&g_xl[src * HC];
    float* np = &g_num[dst * HC];
    float exh[2] = { ex0, ex1 };
    #pragma unroll
    for (int q = 0; q < 5; q++) {
        float4 l = xl4[q];
        float sx = exh[(q * 4 + 0) / 10];
        float sy = exh[(q * 4 + 1) / 10];
        float sz = exh[(q * 4 + 2) / 10];
        float sw = exh[(q * 4 + 3) / 10];
        float4 v = make_float4(l.x * sx, l.y * sy, l.z * sz, l.w * sw);
        asm volatile("red.global.add.v4.f32 [%0], {%1,%2,%3,%4};"
                     :: "l"(np + q * 4), "f"(v.x), "f"(v.y), "f"(v.z), "f"(v.w)
                     : "memory");
    }
}

// ---------------- kernel D: normalize+bias -> Linear(20,512) -> Linear(512,128)
__global__ void __launch_bounds__(128)
k_out(const float* __restrict__ gat_bias,
      const float* __restrict__ W3, const float* __restrict__ b3,
      const float* __restrict__ W4, const float* __restrict__ b4,
      float* __restrict__ out)
{
    __shared__ float s20[TILE_R][HC];
    __shared__ float hs[TILE_R][H2 + 2];   // +2 pad keeps 8B alignment, breaks conflicts
    const int t = threadIdx.x;
    const int row0 = blockIdx.x * TILE_R;

    for (int o = t; o < TILE_R * HC; o += 128) {
        int r = o / HC, j = o % HC, n = row0 + r, h = j / 10;
        s20[r][j] = g_num[n * HC + j] / (g_den[n * 2 + h] + 1e-16f) + gat_bias[j];
    }
    __syncthreads();

    float acc[4][TILE_R];
    #pragma unroll
    for (int j = 0; j < 4; j++)
        #pragma unroll
        for (int r = 0; r < TILE_R; r++) acc[j][r] = 0.f;

    #pragma unroll
    for (int k = 0; k < HC; k++) {
        float w0 = W3[k * H2 + t];
        float w1 = W3[k * H2 + t + 128];
        float w2 = W3[k * H2 + t + 256];
        float w3 = W3[k * H2 + t + 384];
        #pragma unroll
        for (int r = 0; r < TILE_R; r++) {
            float xv = s20[r][k];
            acc[0][r] += xv * w0;
            acc[1][r] += xv * w1;
            acc[2][r] += xv * w2;
            acc[3][r] += xv * w3;
        }
    }
    #pragma unroll
    for (int j = 0; j < 4; j++) {
        int h = t + 128 * j;
        float bb = b3[h];
        #pragma unroll
        for (int r = 0; r < TILE_R; r++) hs[r][h] = acc[j][r] + bb;
    }
    __syncthreads();

    // out = hs @ W4 + b4 ; thread t owns output column t (CYD == 128)
    float oacc[TILE_R];
    #pragma unroll
    for (int r = 0; r < TILE_R; r++) oacc[r] = 0.f;
    #pragma unroll 2
    for (int k = 0; k < H2; k += 2) {
        float w0 = W4[k * CYD + t];
        float w1 = W4[(k + 1) * CYD + t];
        #pragma unroll
        for (int r = 0; r < TILE_R; r++) {
            float2 hv = *(const float2*)&hs[r][k];
            oacc[r] += hv.x * w0;
            oacc[r] += hv.y * w1;
        }
    }
    float bo = b4[t];
    #pragma unroll
    for (int r = 0; r < TILE_R; r++)
        out[(row0 + r) * CYD + t] = oacc[r] + bo;
}

// ---------------- launch ----------------
// inputs (metadata order): 0 signal, 1 edge_index, 2 edge_weight, 3 mask,
// 4 W1, 5 b1, 6 gamma, 7 beta, 8 W2, 9 b2, 10 Wl, 11 bl, 12 Wr, 13 br,
// 14 We, 15 att, 16 gat_bias, 17 W3, 18 b3, 19 W4, 20 b4
extern "C" void kernel_launch(void* const* d_in, const int* in_sizes, int n_in,
                              void* d_out, int out_size)
{
    const float* signal = (const float*)d_in[0];
    const int*   ei     = (const int*)  d_in[1];
    const float* ew     = (const float*)d_in[2];
    const void*  mask   =               d_in[3];
    const float* W1 = (const float*)d_in[4];
    const float* b1 = (const float*)d_in[5];
    const float* ga = (const float*)d_in[6];
    const float* be = (const float*)d_in[7];
    const float* W2 = (const float*)d_in[8];
    const float* b2 = (const float*)d_in[9];
    const float* Wl = (const float*)d_in[10];
    const float* bl = (const float*)d_in[11];
    const float* Wr = (const float*)d_in[12];
    const float* br = (const float*)d_in[13];
    const float* We = (const float*)d_in[14];
    const float* att = (const float*)d_in[15];
    const float* gb  = (const float*)d_in[16];
    const float* W3 = (const float*)d_in[17];
    const float* b3 = (const float*)d_in[18];
    const float* W4 = (const float*)d_in[19];
    const float* b4 = (const float*)d_in[20];
    float* out = (float*)d_out;

    k_detect<<<1, 256>>>((const unsigned*)mask);
    k_init<<<(NN * HC + 255) / 256, 256>>>();
    k_mlp_in<<<NN / TILE_R, 128>>>(signal, mask, W1, b1, ga, be, W2, b2);
    k_gat_lin<<<(NN * HC + 255) / 256, 256>>>(Wl, bl, Wr, br);
    k_edge1<<<(EE + 255) / 256, 256>>>(ei, ew, We, att);
    k_edge2<<<(EE + 255) / 256, 256>>>(ei);
    k_out<<<NN / TILE_R, 128>>>(gb, W3, b3, W4, b4, out);
}

// round 2
// speedup vs baseline: 1.0498x; 1.0498x over previous
#include <cuda_runtime.h>
#include <math_constants.h>

// Problem constants (fixed by reference)
#define NN      100000      // nodes
#define EE      3200000     // edges
#define CYD     128         // signal channels
#define H1      512         // mlp_in hidden
#define FD      10          // node feature dim after mlp_in
#define HC      20          // heads * out channels (2*10)
#define H2      512         // mlp_out hidden
#define TILE_R  16          // rows per block in GEMM kernels
#define RPAD    (TILE_R + 4)   // padded transposed-row stride (16B-aligned quads)

// ---------------- device scratch (no allocations allowed) ----------------
__device__ float    g_x2[NN * FD];
__device__ float    g_xl[NN * HC];
__device__ float    g_xr[NN * HC];
__device__ float    g_alpha[EE * 2];
__device__ unsigned g_m[NN * 2];
__device__ float    g_den[NN * 2];
__device__ float    g_num[NN * HC];
__device__ int      g_mask_mode;

// ---------------- packed f32x2 helpers (FFMA2 path, PTX-only) ------------
__device__ __forceinline__ unsigned long long pack2(float a, float b) {
    unsigned long long r;
    asm("mov.b64 %0, {%1, %2};" : "=l"(r) : "f"(a), "f"(b));
    return r;
}
__device__ __forceinline__ float2 unpack2(unsigned long long v) {
    float2 r;
    asm("mov.b64 {%0, %1}, %2;" : "=f"(r.x), "=f"(r.y) : "l"(v));
    return r;
}
__device__ __forceinline__ void fma2(unsigned long long& acc,
                                     unsigned long long a, unsigned long long b) {
    asm("fma.rn.f32x2 %0, %1, %2, %0;" : "+l"(acc) : "l"(a), "l"(b));
}
__device__ __forceinline__ unsigned long long add2(unsigned long long a,
                                                   unsigned long long b) {
    unsigned long long r;
    asm("add.rn.f32x2 %0, %1, %2;" : "=l"(r) : "l"(a), "l"(b));
    return r;
}

// ordered-uint encoding so unsigned atomicMax == float max
__device__ __forceinline__ unsigned fenc(float f) {
    unsigned u = __float_as_uint(f);
    return (u & 0x80000000u) ? ~u : (u | 0x80000000u);
}
__device__ __forceinline__ float fdec(unsigned u) {
    return (u & 0x80000000u) ? __uint_as_float(u ^ 0x80000000u)
                             : __uint_as_float(~u);
}

// ---------------- mask dtype detection ----------------
__global__ void k_detect(const unsigned* __restrict__ mw) {
    __shared__ int notInt, notFloat;
    if (threadIdx.x == 0) { notInt = 0; notFloat = 0; }
    __syncthreads();
    unsigned v = mw[threadIdx.x];
    if (v > 1u)                      atomicOr(&notInt, 1);
    if (v != 0u && v != 0x3f800000u) atomicOr(&notFloat, 1);
    __syncthreads();
    if (threadIdx.x == 0)
        g_mask_mode = notInt ? (notFloat ? 0 : 2) : 1;
}

// ---------------- init accumulators ----------------
__global__ void k_init() {
    int i = blockIdx.x * blockDim.x + threadIdx.x;
    if (i < NN * HC) g_num[i] = 0.f;
    if (i < NN * 2) { g_den[i] = 0.f; g_m[i] = fenc(-CUDART_INF_F); }
}

// ---- kernel A: mask -> Linear(128,512) -> BN -> ReLU -> Linear(512,10) ----
__global__ void __launch_bounds__(128)
k_mlp_in(const float* __restrict__ signal, const void* __restrict__ mask,
         const float* __restrict__ W1, const float* __restrict__ b1,
         const float* __restrict__ gamma, const float* __restrict__ beta,
         const float* __restrict__ W2, const float* __restrict__ b2)
{
    __shared__ __align__(16) float xs[CYD][RPAD];      // transposed input tile
    __shared__ __align__(16) float hs[TILE_R][H1 + 2]; // hidden (row-major)
    const int t = threadIdx.x;
    const int row0 = blockIdx.x * TILE_R;
    const int mode = g_mask_mode;

    // load transposed: xs[channel][row]
    #pragma unroll
    for (int r = 0; r < TILE_R; r++) {
        int n = row0 + r;
        bool mk;
        if (mode == 0)      mk = ((const unsigned char*)mask)[n] != 0;
        else if (mode == 1) mk = ((const int*)mask)[n] != 0;
        else                mk = ((const float*)mask)[n] != 0.f;
        xs[t][r] = mk ? 0.f : signal[n * CYD + t];
    }
    __syncthreads();

    // GEMM1: acc[j][p] = packed (row 2p, row 2p+1) for column 4t+j
    unsigned long long acc[4][8];
    #pragma unroll
    for (int j = 0; j < 4; j++)
        #pragma unroll
        for (int p = 0; p < 8; p++) acc[j][p] = 0ull;

    #pragma unroll 2
    for (int k = 0; k < CYD; k++) {
        float4 w = *(const float4*)&W1[k * H1 + 4 * t];
        unsigned long long wp0 = pack2(w.x, w.x);
        unsigned long long wp1 = pack2(w.y, w.y);
        unsigned long long wp2 = pack2(w.z, w.z);
        unsigned long long wp3 = pack2(w.w, w.w);
        #pragma unroll
        for (int q = 0; q < 4; q++) {
            ulonglong2 xv = *(const ulonglong2*)&xs[k][4 * q];  // rows 4q..4q+3
            fma2(acc[0][2 * q], xv.x, wp0);
            fma2(acc[1][2 * q], xv.x, wp1);
            fma2(acc[2][2 * q], xv.x, wp2);
            fma2(acc[3][2 * q], xv.x, wp3);
            fma2(acc[0][2 * q + 1], xv.y, wp0);
            fma2(acc[1][2 * q + 1], xv.y, wp1);
            fma2(acc[2][2 * q + 1], xv.y, wp2);
            fma2(acc[3][2 * q + 1], xv.y, wp3);
        }
    }

    // bias + BN + ReLU, write row-major hidden
    const float inv = rsqrtf(1.f + 1e-5f);
    #pragma unroll
    for (int j = 0; j < 4; j++) {
        int h = 4 * t + j;
        float s  = gamma[h] * inv;
        float bb = beta[h];
        float bi = b1[h];
        #pragma unroll
        for (int p = 0; p < 8; p++) {
            float2 v = unpack2(acc[j][p]);
            float v0 = (v.x + bi) * s + bb;
            float v1 = (v.y + bi) * s + bb;
            hs[2 * p][h]     = v0 > 0.f ? v0 : 0.f;
            hs[2 * p + 1][h] = v1 > 0.f ? v1 : 0.f;
        }
    }
    __syncthreads();

    // x2 = hs @ W2 + b2 (16x10 outputs)
    for (int o = t; o < TILE_R * FD; o += 128) {
        int r = o / FD, c = o % FD;
        float a = b2[c];
        #pragma unroll 8
        for (int h = 0; h < H1; h++) a += hs[r][h] * W2[h * FD + c];
        g_x2[(row0 + r) * FD + c] = a;
    }
}

// ---- kernel B: xl = x2@Wl+bl ; xr = x2@Wr+br ----
__global__ void k_gat_lin(const float* __restrict__ Wl, const float* __restrict__ bl,
                          const float* __restrict__ Wr, const float* __restrict__ br)
{
    int i = blockIdx.x * blockDim.x + threadIdx.x;
    if (i >= NN * HC) return;
    int n = i / HC, j = i % HC;
    const float* x = &g_x2[n * FD];
    float al = bl[j], ar = br[j];
    #pragma unroll
    for (int k = 0; k < FD; k++) {
        float xv = x[k];
        al += xv * Wl[k * HC + j];
        ar += xv * Wr[k * HC + j];
    }
    g_xl[i] = al;
    g_xr[i] = ar;
}

// ---- kernel C1: per-edge attention logit + segment max ----
__global__ void k_edge1(const int* __restrict__ ei, const float* __restrict__ ew,
                        const float* __restrict__ We, const float* __restrict__ att)
{
    int e = blockIdx.x * blockDim.x + threadIdx.x;
    if (e >= EE) return;
    int src = ei[e], dst = ei[EE + e];
    float w = ew[e];
    const float4* xl4 = (const float4*)&g_xl[src * HC];
    const float4* xr4 = (const float4*)&g_xr[dst * HC];
    float a0 = 0.f, a1 = 0.f;
    #pragma unroll
    for (int q = 0; q < 5; q++) {
        float4 l = xl4[q], r = xr4[q];
        float vv[4] = { l.x + r.x, l.y + r.y, l.z + r.z, l.w + r.w };
        #pragma unroll
        for (int u = 0; u < 4; u++) {
            int j = q * 4 + u;
            float v = vv[u] + w * We[j];
            v = v > 0.f ? v : 0.2f * v;
            if (j < 10) a0 += v * att[j];
            else        a1 += v * att[j];
        }
    }
    g_alpha[2 * e]     = a0;
    g_alpha[2 * e + 1] = a1;
    atomicMax(&g_m[dst * 2],     fenc(a0));
    atomicMax(&g_m[dst * 2 + 1], fenc(a1));
}

// ---- kernel C2: exp + unnormalized scatter-accumulate ----
__global__ void k_edge2(const int* __restrict__ ei)
{
    int e = blockIdx.x * blockDim.x + threadIdx.x;
    if (e >= EE) return;
    int src = ei[e], dst = ei[EE + e];
    float ex0 = expf(g_alpha[2 * e]     - fdec(g_m[dst * 2]));
    float ex1 = expf(g_alpha[2 * e + 1] - fdec(g_m[dst * 2 + 1]));
    atomicAdd(&g_den[dst * 2],     ex0);
    atomicAdd(&g_den[dst * 2 + 1], ex1);
    const float4* xl4 = (const float4*)&g_xl[src * HC];
    float* np = &g_num[dst * HC];
    float exh[2] = { ex0, ex1 };
    #pragma unroll
    for (int q = 0; q < 5; q++) {
        float4 l = xl4[q];
        float sx = exh[(q * 4 + 0) / 10];
        float sy = exh[(q * 4 + 1) / 10];
        float sz = exh[(q * 4 + 2) / 10];
        float sw = exh[(q * 4 + 3) / 10];
        float4 v = make_float4(l.x * sx, l.y * sy, l.z * sz, l.w * sw);
        asm volatile("red.global.add.v4.f32 [%0], {%1,%2,%3,%4};"
                     :: "l"(np + q * 4), "f"(v.x), "f"(v.y), "f"(v.z), "f"(v.w)
                     : "memory");
    }
}

// ---- kernel D: normalize+bias -> Linear(20,512) -> Linear(512,128) ----
__global__ void __launch_bounds__(128)
k_out(const float* __restrict__ gat_bias,
      const float* __restrict__ W3, const float* __restrict__ b3,
      const float* __restrict__ W4, const float* __restrict__ b4,
      float* __restrict__ out)
{
    __shared__ __align__(16) float s20[HC][RPAD];   // transposed GAT features
    __shared__ __align__(16) float hst[H2][RPAD];   // transposed hidden (40 KB)
    const int t = threadIdx.x;
    const int row0 = blockIdx.x * TILE_R;

    for (int o = t; o < TILE_R * HC; o += 128) {
        int r = o / HC, j = o % HC, n = row0 + r, h = j / 10;
        s20[j][r] = g_num[n * HC + j] / (g_den[n * 2 + h] + 1e-16f) + gat_bias[j];
    }
    __syncthreads();

    // GEMM3: cols 4t..4t+3, packed row pairs
    unsigned long long acc[4][8];
    #pragma unroll
    for (int j = 0; j < 4; j++)
        #pragma unroll
        for (int p = 0; p < 8; p++) acc[j][p] = 0ull;

    #pragma unroll
    for (int k = 0; k < HC; k++) {
        float4 w = *(const float4*)&W3[k * H2 + 4 * t];
        unsigned long long wp0 = pack2(w.x, w.x);
        unsigned long long wp1 = pack2(w.y, w.y);
        unsigned long long wp2 = pack2(w.z, w.z);
        unsigned long long wp3 = pack2(w.w, w.w);
        #pragma unroll
        for (int q = 0; q < 4; q++) {
            ulonglong2 xv = *(const ulonglong2*)&s20[k][4 * q];
            fma2(acc[0][2 * q], xv.x, wp0);
            fma2(acc[1][2 * q], xv.x, wp1);
            fma2(acc[2][2 * q], xv.x, wp2);
            fma2(acc[3][2 * q], xv.x, wp3);
            fma2(acc[0][2 * q + 1], xv.y, wp0);
            fma2(acc[1][2 * q + 1], xv.y, wp1);
            fma2(acc[2][2 * q + 1], xv.y, wp2);
            fma2(acc[3][2 * q + 1], xv.y, wp3);
        }
    }
    // + b3, store transposed as packed 64-bit rows
    #pragma unroll
    for (int j = 0; j < 4; j++) {
        int h = 4 * t + j;
        unsigned long long bb = pack2(b3[h], b3[h]);
        #pragma unroll
        for (int p = 0; p < 8; p++)
            *(unsigned long long*)&hst[h][2 * p] = add2(acc[j][p], bb);
    }
    __syncthreads();

    // GEMM4: out column t, packed row pairs
    unsigned long long oacc[8];
    #pragma unroll
    for (int p = 0; p < 8; p++) oacc[p] = 0ull;
    #pragma unroll 4
    for (int k = 0; k < H2; k++) {
        float w = W4[k * CYD + t];
        unsigned long long wp = pack2(w, w);
        #pragma unroll
        for (int q = 0; q < 4; q++) {
            ulonglong2 xv = *(const ulonglong2*)&hst[k][4 * q];
            fma2(oacc[2 * q],     xv.x, wp);
            fma2(oacc[2 * q + 1], xv.y, wp);
        }
    }
    float bo = b4[t];
    #pragma unroll
    for (int p = 0; p < 8; p++) {
        float2 v = unpack2(oacc[p]);
        out[(row0 + 2 * p)     * CYD + t] = v.x + bo;
        out[(row0 + 2 * p + 1) * CYD + t] = v.y + bo;
    }
}

// ---------------- launch ----------------
extern "C" void kernel_launch(void* const* d_in, const int* in_sizes, int n_in,
                              void* d_out, int out_size)
{
    const float* signal = (const float*)d_in[0];
    const int*   ei     = (const int*)  d_in[1];
    const float* ew     = (const float*)d_in[2];
    const void*  mask   =               d_in[3];
    const float* W1 = (const float*)d_in[4];
    const float* b1 = (const float*)d_in[5];
    const float* ga = (const float*)d_in[6];
    const float* be = (const float*)d_in[7];
    const float* W2 = (const float*)d_in[8];
    const float* b2 = (const float*)d_in[9];
    const float* Wl = (const float*)d_in[10];
    const float* bl = (const float*)d_in[11];
    const float* Wr = (const float*)d_in[12];
    const float* br = (const float*)d_in[13];
    const float* We = (const float*)d_in[14];
    const float* att = (const float*)d_in[15];
    const float* gb  = (const float*)d_in[16];
    const float* W3 = (const float*)d_in[17];
    const float* b3 = (const float*)d_in[18];
    const float* W4 = (const float*)d_in[19];
    const float* b4 = (const float*)d_in[20];
    float* out = (float*)d_out;

    k_detect<<<1, 256>>>((const unsigned*)mask);
    k_init<<<(NN * HC + 255) / 256, 256>>>();
    k_mlp_in<<<NN / TILE_R, 128>>>(signal, mask, W1, b1, ga, be, W2, b2);
    k_gat_lin<<<(NN * HC + 255) / 256, 256>>>(Wl, bl, Wr, br);
    k_edge1<<<(EE + 255) / 256, 256>>>(ei, ew, We, att);
    k_edge2<<<(EE + 255) / 256, 256>>>(ei);
    k_out<<<NN / TILE_R, 128>>>(gb, W3, b3, W4, b4, out);
}

// round 7
// speedup vs baseline: 1.9063x; 1.8159x over previous
#include <cuda_runtime.h>
#include <cuda_bf16.h>
#include <math_constants.h>
#include <cstdint>

#define NN      100000
#define EE      3200000
#define CYD     128
#define H1      512
#define FD      10
#define HC      20
#define H2      512

// ---------------- device scratch ----------------
__device__ float    g_x2[NN * FD];
__device__ float    g_xl[NN * HC];
__device__ float    g_xr[NN * HC];
__device__ float    g_alpha[EE * 2];
__device__ unsigned g_m[NN * 2];
__device__ float    g_den[NN * 2];
__device__ float    g_num[NN * HC];
__device__ int      g_mask_mode;
// fragment-packed weights: per (n8, ks, lane): {b0_hi, b1_hi, b0_lo, b1_lo}
__device__ uint32_t g_w1frag[(H1 / 8) * (CYD / 16) * 32 * 4];   // 256 KB
__device__ uint32_t g_w3frag[(H2 / 8) * (32 / 16) * 32 * 4];    // 64 KB
__device__ uint32_t g_w4frag[(CYD / 8) * (H2 / 16) * 32 * 4];   // 256 KB

// ---------------- helpers ----------------
__device__ __forceinline__ unsigned long long pack2(float a, float b) {
    unsigned long long r;
    asm("mov.b64 %0, {%1, %2};" : "=l"(r) : "f"(a), "f"(b));
    return r;
}
__device__ __forceinline__ float2 unpack2(unsigned long long v) {
    float2 r;
    asm("mov.b64 {%0, %1}, %2;" : "=f"(r.x), "=f"(r.y) : "l"(v));
    return r;
}
__device__ __forceinline__ void fma2(unsigned long long& acc,
                                     unsigned long long a, unsigned long long b) {
    asm("fma.rn.f32x2 %0, %1, %2, %0;" : "+l"(acc) : "l"(a), "l"(b));
}
__device__ __forceinline__ unsigned fenc(float f) {
    unsigned u = __float_as_uint(f);
    return (u & 0x80000000u) ? ~u : (u | 0x80000000u);
}
__device__ __forceinline__ float fdec(unsigned u) {
    return (u & 0x80000000u) ? __uint_as_float(u ^ 0x80000000u)
                             : __uint_as_float(~u);
}
__device__ __forceinline__ uint32_t pk_bf2(float a, float b) {
    __nv_bfloat162 h = __floats2bfloat162_rn(a, b);
    return *(uint32_t*)&h;
}
// D += A * B  (m16n8k16, bf16 in, fp32 acc)
__device__ __forceinline__ void mma_bf16(float* c, const uint32_t* a, uint32_t b0, uint32_t b1) {
    asm volatile("mma.sync.aligned.m16n8k16.row.col.f32.bf16.bf16.f32 "
                 "{%0,%1,%2,%3}, {%4,%5,%6,%7}, {%8,%9}, {%0,%1,%2,%3};"
                 : "+f"(c[0]), "+f"(c[1]), "+f"(c[2]), "+f"(c[3])
                 : "r"(a[0]), "r"(a[1]), "r"(a[2]), "r"(a[3]), "r"(b0), "r"(b1));
}

// ---------------- mask dtype detection ----------------
__global__ void k_detect(const unsigned* __restrict__ mw) {
    __shared__ int notInt, notFloat;
    if (threadIdx.x == 0) { notInt = 0; notFloat = 0; }
    __syncthreads();
    unsigned v = mw[threadIdx.x];
    if (v > 1u)                      atomicOr(&notInt, 1);
    if (v != 0u && v != 0x3f800000u) atomicOr(&notFloat, 1);
    __syncthreads();
    if (threadIdx.x == 0)
        g_mask_mode = notInt ? (notFloat ? 0 : 2) : 1;
}

// ---------------- init ----------------
__global__ void k_init() {
    int i = blockIdx.x * blockDim.x + threadIdx.x;
    if (i < NN * HC) g_num[i] = 0.f;
    if (i < NN * 2) { g_den[i] = 0.f; g_m[i] = fenc(-CUDART_INF_F); }
}

// ---------------- weight fragment prep: W[K][N] -> frag(hi/lo) ----------------
__global__ void k_prep(const float* __restrict__ W, uint32_t* __restrict__ frag,
                       int Kreal, int Kpad, int Nn)
{
    int i = blockIdx.x * blockDim.x + threadIdx.x;
    int kp2 = Kpad >> 1;
    if (i >= Nn * kp2) return;
    int n = i / kp2, k = (i % kp2) * 2;
    float w0 = (k     < Kreal) ? W[(size_t)k * Nn + n]       : 0.f;
    float w1 = (k + 1 < Kreal) ? W[(size_t)(k + 1) * Nn + n] : 0.f;
    float h0f = __bfloat162float(__float2bfloat16(w0));
    float h1f = __bfloat162float(__float2bfloat16(w1));
    uint32_t whi = pk_bf2(h0f, h1f);
    uint32_t wlo = pk_bf2(w0 - h0f, w1 - h1f);
    int n8 = n >> 3, ks = k >> 4;
    int lane = ((n & 7) << 2) | ((k & 7) >> 1);
    int b01 = (k >> 3) & 1;
    int base = ((n8 * (Kpad >> 4) + ks) * 32 + lane) * 4;
    frag[base + b01]     = whi;
    frag[base + 2 + b01] = wlo;
}

// =====================================================================
// kernel A: mask -> GEMM1(mma bf16 3-pass) -> BN -> ReLU -> GEMM2
// CTA: 128 rows, 256 threads (8 warps: 4 m-stripes x 2 n-halves)
// =====================================================================
#define A_STRIDE 136                  // bf16 elems per row (pad)
#define OFF_AHI  0
#define OFF_ALO  34816
#define OFF_HSF  69632                // float2[64][128]
#define OFF_W2T  135168               // float [10][512]
#define OFF_B1   155648
#define OFF_SC   157696
#define OFF_BE   159744
#define SM1_TOTAL 161792

__global__ void __launch_bounds__(256, 1)
k_mlp_mma(const float* __restrict__ signal, const void* __restrict__ mask,
          const float* __restrict__ W2, const float* __restrict__ b1,
          const float* __restrict__ gamma, const float* __restrict__ beta,
          const float* __restrict__ b2)
{
    extern __shared__ char smem[];
    __nv_bfloat16* Ahi = (__nv_bfloat16*)(smem + OFF_AHI);
    __nv_bfloat16* Alo = (__nv_bfloat16*)(smem + OFF_ALO);
    float2* hsf2 = (float2*)(smem + OFF_HSF);
    float*  w2t  = (float*)(smem + OFF_W2T);
    float*  sb1  = (float*)(smem + OFF_B1);
    float*  ssc  = (float*)(smem + OFF_SC);
    float*  sbe  = (float*)(smem + OFF_BE);

    const int tid = threadIdx.x;
    const int lane = tid & 31;
    const int wid  = tid >> 5;
    const int wm = wid & 3, wn = wid >> 2;
    const int g  = lane >> 2, q4 = lane & 3;
    const int row0 = blockIdx.x * 128;

    // params
    const float inv = rsqrtf(1.f + 1e-5f);
    for (int i = tid; i < H1; i += 256) {
        sb1[i] = b1[i];
        ssc[i] = gamma[i] * inv;
        sbe[i] = beta[i];
    }
    for (int i = tid; i < H1 * FD; i += 256) {
        int c = i / H1, k = i % H1;
        w2t[c * H1 + k] = W2[(size_t)k * FD + c];
    }

    // A: rows -> smem bf16 hi/lo (masked)
    {
        const int r = tid >> 1, ch = tid & 1;
        const int n = row0 + r;
        const int mode = g_mask_mode;
        bool ok = (n < NN);
        if (ok) {
            bool mk;
            if (mode == 0)      mk = ((const unsigned char*)mask)[n] != 0;
            else if (mode == 1) mk = ((const int*)mask)[n] != 0;
            else                mk = ((const float*)mask)[n] != 0.f;
            ok = !mk;
        }
        const float4* xp = (const float4*)&signal[(size_t)(n < NN ? n : 0) * CYD + ch * 64];
        #pragma unroll
        for (int qq = 0; qq < 8; qq++) {
            float4 v0 = ok ? xp[2 * qq]     : make_float4(0, 0, 0, 0);
            float4 v1 = ok ? xp[2 * qq + 1] : make_float4(0, 0, 0, 0);
            float f[8] = { v0.x, v0.y, v0.z, v0.w, v1.x, v1.y, v1.z, v1.w };
            float fh[8];
            #pragma unroll
            for (int u = 0; u < 8; u++) fh[u] = __bfloat162float(__float2bfloat16(f[u]));
            uint4 hi = make_uint4(pk_bf2(fh[0], fh[1]), pk_bf2(fh[2], fh[3]),
                                  pk_bf2(fh[4], fh[5]), pk_bf2(fh[6], fh[7]));
            uint4 lo = make_uint4(pk_bf2(f[0] - fh[0], f[1] - fh[1]), pk_bf2(f[2] - fh[2], f[3] - fh[3]),
                                  pk_bf2(f[4] - fh[4], f[5] - fh[5]), pk_bf2(f[6] - fh[6], f[7] - fh[7]));
            int eoff = r * A_STRIDE + ch * 64 + qq * 8;
            *(uint4*)&Ahi[eoff] = hi;
            *(uint4*)&Alo[eoff] = lo;
        }
    }
    __syncthreads();

    unsigned long long acc2[5];
    #pragma unroll
    for (int j = 0; j < 5; j++) acc2[j] = 0ull;
    const int r2 = tid & 127, grp = tid >> 7;

    for (int nt = 0; nt < 4; nt++) {
        float acc[2][8][4];
        #pragma unroll
        for (int mt = 0; mt < 2; mt++)
            #pragma unroll
            for (int j = 0; j < 8; j++)
                #pragma unroll
                for (int c = 0; c < 4; c++) acc[mt][j][c] = 0.f;

        #pragma unroll
        for (int ks = 0; ks < 8; ks++) {
            const int k0 = ks * 16 + q4 * 2;
            uint32_t ah[2][4], al[2][4];
            #pragma unroll
            for (int mt = 0; mt < 2; mt++) {
                int ra = wm * 32 + mt * 16 + g;
                ah[mt][0] = *(const uint32_t*)&Ahi[ra * A_STRIDE + k0];
                ah[mt][1] = *(const uint32_t*)&Ahi[(ra + 8) * A_STRIDE + k0];
                ah[mt][2] = *(const uint32_t*)&Ahi[ra * A_STRIDE + k0 + 8];
                ah[mt][3] = *(const uint32_t*)&Ahi[(ra + 8) * A_STRIDE + k0 + 8];
                al[mt][0] = *(const uint32_t*)&Alo[ra * A_STRIDE + k0];
                al[mt][1] = *(const uint32_t*)&Alo[(ra + 8) * A_STRIDE + k0];
                al[mt][2] = *(const uint32_t*)&Alo[ra * A_STRIDE + k0 + 8];
                al[mt][3] = *(const uint32_t*)&Alo[(ra + 8) * A_STRIDE + k0 + 8];
            }
            #pragma unroll
            for (int j = 0; j < 8; j++) {
                int n8 = nt * 16 + wn * 8 + j;
                const uint4 bv = *(const uint4*)&g_w1frag[((n8 * 8 + ks) * 32 + lane) * 4];
                #pragma unroll
                for (int mt = 0; mt < 2; mt++) {
                    mma_bf16(acc[mt][j], ah[mt], bv.x, bv.y);
                    mma_bf16(acc[mt][j], ah[mt], bv.z, bv.w);
                    mma_bf16(acc[mt][j], al[mt], bv.x, bv.y);
                }
            }
        }

        // epilogue: BN + ReLU -> hsf2[cp][row]
        #pragma unroll
        for (int j = 0; j < 8; j++) {
            int hcol = nt * 128 + wn * 64 + j * 8 + q4 * 2;
            float s0 = ssc[hcol], s1 = ssc[hcol + 1];
            float bi0 = sb1[hcol], bi1 = sb1[hcol + 1];
            float be0 = sbe[hcol], be1 = sbe[hcol + 1];
            int cp = wn * 32 + j * 4 + q4;
            #pragma unroll
            for (int mt = 0; mt < 2; mt++) {
                int ra = wm * 32 + mt * 16 + g;
                float v0 = fmaxf((acc[mt][j][0] + bi0) * s0 + be0, 0.f);
                float v1 = fmaxf((acc[mt][j][1] + bi1) * s1 + be1, 0.f);
                float v2 = fmaxf((acc[mt][j][2] + bi0) * s0 + be0, 0.f);
                float v3 = fmaxf((acc[mt][j][3] + bi1) * s1 + be1, 0.f);
                hsf2[cp * 128 + ra]     = make_float2(v0, v1);
                hsf2[cp * 128 + ra + 8] = make_float2(v2, v3);
            }
        }
        __syncthreads();

        // GEMM2 partial over this 128-col chunk
        {
            #pragma unroll 8
            for (int cp = 0; cp < 64; cp++) {
                float2 h = hsf2[cp * 128 + r2];
                unsigned long long hp = pack2(h.x, h.y);
                #pragma unroll
                for (int j = 0; j < 5; j++) {
                    const float2 w = *(const float2*)&w2t[(grp * 5 + j) * H1 + nt * 128 + cp * 2];
                    fma2(acc2[j], hp, pack2(w.x, w.y));
                }
            }
        }
        __syncthreads();
    }

    // write x2
    {
        int n = row0 + r2;
        if (n < NN) {
            #pragma unroll
            for (int j = 0; j < 5; j++) {
                float2 u = unpack2(acc2[j]);
                g_x2[(size_t)n * FD + grp * 5 + j] = u.x + u.y + b2[grp * 5 + j];
            }
        }
    }
}

// ---------------- xl/xr linear ----------------
__global__ void k_gat_lin(const float* __restrict__ Wl, const float* __restrict__ bl,
                          const float* __restrict__ Wr, const float* __restrict__ br)
{
    int i = blockIdx.x * blockDim.x + threadIdx.x;
    if (i >= NN * HC) return;
    int n = i / HC, j = i % HC;
    const float* x = &g_x2[n * FD];
    float al = bl[j], ar = br[j];
    #pragma unroll
    for (int k = 0; k < FD; k++) {
        float xv = x[k];
        al += xv * Wl[k * HC + j];
        ar += xv * Wr[k * HC + j];
    }
    g_xl[i] = al;
    g_xr[i] = ar;
}

// ---------------- edge pass 1 ----------------
__global__ void k_edge1(const int* __restrict__ ei, const float* __restrict__ ew,
                        const float* __restrict__ We, const float* __restrict__ att)
{
    int e = blockIdx.x * blockDim.x + threadIdx.x;
    if (e >= EE) return;
    int src = ei[e], dst = ei[EE + e];
    float w = ew[e];
    const float4* xl4 = (const float4*)&g_xl[src * HC];
    const float4* xr4 = (const float4*)&g_xr[dst * HC];
    float a0 = 0.f, a1 = 0.f;
    #pragma unroll
    for (int q = 0; q < 5; q++) {
        float4 l = xl4[q], r = xr4[q];
        float vv[4] = { l.x + r.x, l.y + r.y, l.z + r.z, l.w + r.w };
        #pragma unroll
        for (int u = 0; u < 4; u++) {
            int j = q * 4 + u;
            float v = vv[u] + w * We[j];
            v = v > 0.f ? v : 0.2f * v;
            if (j < 10) a0 += v * att[j];
            else        a1 += v * att[j];
        }
    }
    g_alpha[2 * e]     = a0;
    g_alpha[2 * e + 1] = a1;
    atomicMax(&g_m[dst * 2],     fenc(a0));
    atomicMax(&g_m[dst * 2 + 1], fenc(a1));
}

// ---------------- edge pass 2 ----------------
__global__ void k_edge2(const int* __restrict__ ei)
{
    int e = blockIdx.x * blockDim.x + threadIdx.x;
    if (e >= EE) return;
    int src = ei[e], dst = ei[EE + e];
    float ex0 = expf(g_alpha[2 * e]     - fdec(g_m[dst * 2]));
    float ex1 = expf(g_alpha[2 * e + 1] - fdec(g_m[dst * 2 + 1]));
    atomicAdd(&g_den[dst * 2],     ex0);
    atomicAdd(&g_den[dst * 2 + 1], ex1);
    const float4* xl4 = (const float4*)&g_xl[src * HC];
    float* np = &g_num[dst * HC];
    float exh[2] = { ex0, ex1 };
    #pragma unroll
    for (int q = 0; q < 5; q++) {
        float4 l = xl4[q];
        float sx = exh[(q * 4 + 0) / 10];
        float sy = exh[(q * 4 + 1) / 10];
        float sz = exh[(q * 4 + 2) / 10];
        float sw = exh[(q * 4 + 3) / 10];
        float4 v = make_float4(l.x * sx, l.y * sy, l.z * sz, l.w * sw);
        asm volatile("red.global.add.v4.f32 [%0], {%1,%2,%3,%4};"
                     :: "l"(np + q * 4), "f"(v.x), "f"(v.y), "f"(v.z), "f"(v.w)
                     : "memory");
    }
}

// =====================================================================
// kernel D: GAT normalize -> GEMM3(mma,k pad 32) -> GEMM4(mma) -> out
// CTA: 128 rows, 256 threads
// =====================================================================
#define A3_STRIDE 40
#define H_STRIDE  136
#define OFF_A3H   0
#define OFF_A3L   10240
#define OFF_HH    20480
#define OFF_HL    55296
#define SM2_TOTAL 90112

__global__ void __launch_bounds__(256, 1)
k_out_mma(const float* __restrict__ gat_bias,
          const float* __restrict__ b3, const float* __restrict__ b4,
          float* __restrict__ out)
{
    extern __shared__ char smem[];
    __nv_bfloat16* A3h = (__nv_bfloat16*)(smem + OFF_A3H);
    __nv_bfloat16* A3l = (__nv_bfloat16*)(smem + OFF_A3L);
    __nv_bfloat16* Hh  = (__nv_bfloat16*)(smem + OFF_HH);
    __nv_bfloat16* Hl  = (__nv_bfloat16*)(smem + OFF_HL);

    const int tid = threadIdx.x;
    const int lane = tid & 31;
    const int wid  = tid >> 5;
    const int wm = wid & 3, wn = wid >> 2;
    const int g = lane >> 2, q4 = lane & 3;
    const int row0 = blockIdx.x * 128;

    // zero pad + load GAT outputs
    for (int i = tid; i < 128 * 32; i += 256) {       // cols 0..31 (zero all then fill 0..19)
        int r = i >> 5, c = i & 31;
        A3h[r * A3_STRIDE + c] = __float2bfloat16(0.f);
        A3l[r * A3_STRIDE + c] = __float2bfloat16(0.f);
    }
    __syncthreads();
    for (int i = tid; i < 128 * HC; i += 256) {
        int r = i / HC, c = i % HC;
        int n = row0 + r;
        float v = 0.f;
        if (n < NN)
            v = g_num[(size_t)n * HC + c] / (g_den[n * 2 + c / 10] + 1e-16f) + gat_bias[c];
        __nv_bfloat16 h = __float2bfloat16(v);
        A3h[r * A3_STRIDE + c] = h;
        A3l[r * A3_STRIDE + c] = __float2bfloat16(v - __bfloat162float(h));
    }
    __syncthreads();

    // b4 per-thread columns
    float2 bw[8];
    #pragma unroll
    for (int j = 0; j < 8; j++)
        bw[j] = *(const float2*)&b4[wn * 64 + j * 8 + q4 * 2];

    float acc4[2][8][4];
    #pragma unroll
    for (int mt = 0; mt < 2; mt++)
        #pragma unroll
        for (int j = 0; j < 8; j++)
            #pragma unroll
            for (int c = 0; c < 4; c++) acc4[mt][j][c] = 0.f;

    for (int nt = 0; nt < 4; nt++) {
        // ---- GEMM3 for hidden cols [nt*128, nt*128+128)
        float acc3[2][8][4];
        #pragma unroll
        for (int mt = 0; mt < 2; mt++)
            #pragma unroll
            for (int j = 0; j < 8; j++)
                #pragma unroll
                for (int c = 0; c < 4; c++) acc3[mt][j][c] = 0.f;

        #pragma unroll
        for (int ks = 0; ks < 2; ks++) {
            const int k0 = ks * 16 + q4 * 2;
            uint32_t ah[2][4], al[2][4];
            #pragma unroll
            for (int mt = 0; mt < 2; mt++) {
                int ra = wm * 32 + mt * 16 + g;
                ah[mt][0] = *(const uint32_t*)&A3h[ra * A3_STRIDE + k0];
                ah[mt][1] = *(const uint32_t*)&A3h[(ra + 8) * A3_STRIDE + k0];
                ah[mt][2] = *(const uint32_t*)&A3h[ra * A3_STRIDE + k0 + 8];
                ah[mt][3] = *(const uint32_t*)&A3h[(ra + 8) * A3_STRIDE + k0 + 8];
                al[mt][0] = *(const uint32_t*)&A3l[ra * A3_STRIDE + k0];
                al[mt][1] = *(const uint32_t*)&A3l[(ra + 8) * A3_STRIDE + k0];
                al[mt][2] = *(const uint32_t*)&A3l[ra * A3_STRIDE + k0 + 8];
                al[mt][3] = *(const uint32_t*)&A3l[(ra + 8) * A3_STRIDE + k0 + 8];
            }
            #pragma unroll
            for (int j = 0; j < 8; j++) {
                int n8 = nt * 16 + wn * 8 + j;
                const uint4 bv = *(const uint4*)&g_w3frag[((n8 * 2 + ks) * 32 + lane) * 4];
                #pragma unroll
                for (int mt = 0; mt < 2; mt++) {
                    mma_bf16(acc3[mt][j], ah[mt], bv.x, bv.y);
                    mma_bf16(acc3[mt][j], ah[mt], bv.z, bv.w);
                    mma_bf16(acc3[mt][j], al[mt], bv.x, bv.y);
                }
            }
        }

        // epilogue: +b3, split bf16 -> Hh/Hl [row][local k]
        #pragma unroll
        for (int j = 0; j < 8; j++) {
            int hcol = nt * 128 + wn * 64 + j * 8 + q4 * 2;
            float2 bb = *(const float2*)&b3[hcol];
            int cl = wn * 64 + j * 8 + q4 * 2;
            #pragma unroll
            for (int mt = 0; mt < 2; mt++) {
                int ra = wm * 32 + mt * 16 + g;
                float v0 = acc3[mt][j][0] + bb.x;
                float v1 = acc3[mt][j][1] + bb.y;
                float v2 = acc3[mt][j][2] + bb.x;
                float v3 = acc3[mt][j][3] + bb.y;
                float h0 = __bfloat162float(__float2bfloat16(v0));
                float h1 = __bfloat162float(__float2bfloat16(v1));
                float h2 = __bfloat162float(__float2bfloat16(v2));
                float h3 = __bfloat162float(__float2bfloat16(v3));
                *(uint32_t*)&Hh[ra * H_STRIDE + cl]       = pk_bf2(h0, h1);
                *(uint32_t*)&Hh[(ra + 8) * H_STRIDE + cl] = pk_bf2(h2, h3);
                *(uint32_t*)&Hl[ra * H_STRIDE + cl]       = pk_bf2(v0 - h0, v1 - h1);
                *(uint32_t*)&Hl[(ra + 8) * H_STRIDE + cl] = pk_bf2(v2 - h2, v3 - h3);
            }
        }
        __syncthreads();

        // ---- GEMM4 accumulate over this 128-k chunk
        #pragma unroll
        for (int ks = 0; ks < 8; ks++) {
            const int k0 = ks * 16 + q4 * 2;
            uint32_t ah[2][4], al[2][4];
            #pragma unroll
            for (int mt = 0; mt < 2; mt++) {
                int ra = wm * 32 + mt * 16 + g;
                ah[mt][0] = *(const uint32_t*)&Hh[ra * H_STRIDE + k0];
                ah[mt][1] = *(const uint32_t*)&Hh[(ra + 8) * H_STRIDE + k0];
                ah[mt][2] = *(const uint32_t*)&Hh[ra * H_STRIDE + k0 + 8];
                ah[mt][3] = *(const uint32_t*)&Hh[(ra + 8) * H_STRIDE + k0 + 8];
                al[mt][0] = *(const uint32_t*)&Hl[ra * H_STRIDE + k0];
                al[mt][1] = *(const uint32_t*)&Hl[(ra + 8) * H_STRIDE + k0];
                al[mt][2] = *(const uint32_t*)&Hl[ra * H_STRIDE + k0 + 8];
                al[mt][3] = *(const uint32_t*)&Hl[(ra + 8) * H_STRIDE + k0 + 8];
            }
            #pragma unroll
            for (int j = 0; j < 8; j++) {
                int n8 = wn * 8 + j;
                int ksg = nt * 8 + ks;
                const uint4 bv = *(const uint4*)&g_w4frag[((n8 * 32 + ksg) * 32 + lane) * 4];
                #pragma unroll
                for (int mt = 0; mt < 2; mt++) {
                    mma_bf16(acc4[mt][j], ah[mt], bv.x, bv.y);
                    mma_bf16(acc4[mt][j], ah[mt], bv.z, bv.w);
                    mma_bf16(acc4[mt][j], al[mt], bv.x, bv.y);
                }
            }
        }
        __syncthreads();
    }

    // final: + b4 -> out
    #pragma unroll
    for (int j = 0; j < 8; j++) {
        int col = wn * 64 + j * 8 + q4 * 2;
        #pragma unroll
        for (int mt = 0; mt < 2; mt++) {
            int ra = row0 + wm * 32 + mt * 16 + g;
            if (ra < NN)
                *(float2*)&out[(size_t)ra * CYD + col] =
                    make_float2(acc4[mt][j][0] + bw[j].x, acc4[mt][j][1] + bw[j].y);
            if (ra + 8 < NN)
                *(float2*)&out[(size_t)(ra + 8) * CYD + col] =
                    make_float2(acc4[mt][j][2] + bw[j].x, acc4[mt][j][3] + bw[j].y);
        }
    }
}

// ---------------- launch ----------------
extern "C" void kernel_launch(void* const* d_in, const int* in_sizes, int n_in,
                              void* d_out, int out_size)
{
    const float* signal = (const float*)d_in[0];
    const int*   ei     = (const int*)  d_in[1];
    const float* ew     = (const float*)d_in[2];
    const void*  mask   =               d_in[3];
    const float* W1 = (const float*)d_in[4];
    const float* b1 = (const float*)d_in[5];
    const float* ga = (const float*)d_in[6];
    const float* be = (const float*)d_in[7];
    const float* W2 = (const float*)d_in[8];
    const float* b2 = (const float*)d_in[9];
    const float* Wl = (const float*)d_in[10];
    const float* bl = (const float*)d_in[11];
    const float* Wr = (const float*)d_in[12];
    const float* br = (const float*)d_in[13];
    const float* We = (const float*)d_in[14];
    const float* att = (const float*)d_in[15];
    const float* gb  = (const float*)d_in[16];
    const float* W3 = (const float*)d_in[17];
    const float* b3 = (const float*)d_in[18];
    const float* W4 = (const float*)d_in[19];
    const float* b4 = (const float*)d_in[20];
    float* out = (float*)d_out;

    static uint32_t* w1f = nullptr;
    static uint32_t* w3f = nullptr;
    static uint32_t* w4f = nullptr;
    if (!w1f) {
        cudaGetSymbolAddress((void**)&w1f, g_w1frag);
        cudaGetSymbolAddress((void**)&w3f, g_w3frag);
        cudaGetSymbolAddress((void**)&w4f, g_w4frag);
        cudaFuncSetAttribute(k_mlp_mma, cudaFuncAttributeMaxDynamicSharedMemorySize, SM1_TOTAL);
        cudaFuncSetAttribute(k_out_mma, cudaFuncAttributeMaxDynamicSharedMemorySize, SM2_TOTAL);
    }

    k_detect<<<1, 256>>>((const unsigned*)mask);
    k_init<<<(NN * HC + 255) / 256, 256>>>();
    k_prep<<<(H1 * CYD / 2 + 255) / 256, 256>>>(W1, w1f, CYD, CYD, H1);
    k_prep<<<(H2 * 32 / 2 + 255) / 256, 256>>>(W3, w3f, HC, 32, H2);
    k_prep<<<(CYD * H2 / 2 + 255) / 256, 256>>>(W4, w4f, H2, H2, CYD);
    k_mlp_mma<<<(NN + 127) / 128, 256, SM1_TOTAL>>>(signal, mask, W2, b1, ga, be, b2);
    k_gat_lin<<<(NN * HC + 255) / 256, 256>>>(Wl, bl, Wr, br);
    k_edge1<<<(EE + 255) / 256, 256>>>(ei, ew, We, att);
    k_edge2<<<(EE + 255) / 256, 256>>>(ei);
    k_out_mma<<<(NN + 127) / 128, 256, SM2_TOTAL>>>(gb, b3, b4, out);
}